// round 10
// baseline (speedup 1.0000x reference)
#include <cuda_runtime.h>
#include <cuda_bf16.h>
#include <cstdint>

// ============================================================================
// Problem constants
// ============================================================================
#define N_ROWS   4096
#define E_DIM    512
#define C_CLS    50257
#define C_PAD    50432          // 197 * 256
#define N_TILES_C 197           // C_PAD / 256
#define N_TILES_M 32            // N_ROWS / 128

#define MTILE 128
#define NTILE 256
#define NCHUNKS 8               // 512 / 64 bf16 per K chunk (128 B per row-chunk)
#define LOG2E 1.44269504f

// ============================================================================
// Device scratch (static — no allocation APIs allowed)
// ============================================================================
__device__ __align__(16) __nv_bfloat16 g_xbf[(size_t)N_ROWS * E_DIM];
__device__ __align__(16) __nv_bfloat16 g_wbf[(size_t)C_PAD * E_DIM];
__device__ float g_invnx[N_ROWS];
__device__ float g_invnw[C_CLS];
__device__ float g_S[N_ROWS];
__device__ float g_cosm[N_ROWS];
__device__ float g_corr[N_ROWS];
__device__ int   g_lab64;

// ============================================================================
// Helpers (base-target PTX only: cp.async / ldmatrix / mma.sync)
// ============================================================================
__device__ __forceinline__ uint32_t smem_to_u32(const void* smem_ptr) {
    uint32_t addr;
    asm("{ .reg .u64 tmp; cvta.to.shared.u64 tmp, %1; cvt.u32.u64 %0, tmp; }"
        : "=r"(addr) : "l"(smem_ptr));
    return addr;
}

#define SMEM_SWIZZLE_128B(o) ((o) ^ (((o) >> 3) & 0x70))

#define CP_ASYNC16(dst, src) \
    asm volatile("cp.async.cg.shared.global [%0], [%1], 16;" \
        :: "r"(dst), "l"(src) : "memory")
#define CP_COMMIT() asm volatile("cp.async.commit_group;" ::: "memory")
#define CP_WAIT(n)  asm volatile("cp.async.wait_group %0;" :: "n"(n) : "memory")

#define LDMATRIX_X4(r0, r1, r2, r3, addr) \
    asm volatile("ldmatrix.sync.aligned.m8n8.x4.shared.b16 {%0,%1,%2,%3}, [%4];" \
        : "=r"(r0), "=r"(r1), "=r"(r2), "=r"(r3) : "r"(addr))

#define MMA_BF16(c, a, b) \
    asm volatile("mma.sync.aligned.m16n8k16.row.col.f32.bf16.bf16.f32 " \
        "{%0,%1,%2,%3}, {%4,%5,%6,%7}, {%8,%9}, {%0,%1,%2,%3};" \
        : "+f"((c)[0]), "+f"((c)[1]), "+f"((c)[2]), "+f"((c)[3]) \
        : "r"((a)[0]), "r"((a)[1]), "r"((a)[2]), "r"((a)[3]), \
          "r"((b)[0]), "r"((b)[1]))

// SMEM layout (dynamic): A0 | A1 | B0 | B1
#define SMEM_A_BYTES 16384      // 128 rows * 128 B
#define SMEM_B_BYTES 32768      // 256 rows * 128 B
#define SMEM_TOTAL   98304      // 2*(16K+32K)

// ============================================================================
// Kernel 0: detect label dtype (int64 vs int32) — deterministic given input
// ============================================================================
__global__ void detect_kernel(const unsigned* __restrict__ lab) {
    __shared__ unsigned acc[256];
    unsigned v = 0;
    for (int i = threadIdx.x; i < N_ROWS / 2; i += 256) v |= lab[2 * i + 1];
    acc[threadIdx.x] = v;
    __syncthreads();
    for (int s = 128; s; s >>= 1) {
        if (threadIdx.x < s) acc[threadIdx.x] |= acc[threadIdx.x + s];
        __syncthreads();
    }
    if (threadIdx.x == 0) g_lab64 = (acc[0] == 0) ? 1 : 0;
}

// ============================================================================
// Kernel 1: row-normalize x and W into bf16 scratch; store inverse norms;
//           zero S; zero-pad W rows [C_CLS, C_PAD)
// ============================================================================
__global__ void prep_kernel(const float* __restrict__ x, const float* __restrict__ w) {
    __shared__ float red[5];
    int r = blockIdx.x;
    int tid = threadIdx.x;             // 128 threads
    bool isx = (r < N_ROWS);
    int rr = isx ? r : r - N_ROWS;

    if (!isx && rr >= C_CLS) {         // zero-pad row
        reinterpret_cast<uint2*>(g_wbf)[(size_t)rr * 128 + tid] = make_uint2(0u, 0u);
        return;
    }

    const float4* s4 = reinterpret_cast<const float4*>(isx ? x : w);
    float4 v = s4[(size_t)rr * 128 + tid];
    float ss = v.x * v.x + v.y * v.y + v.z * v.z + v.w * v.w;
#pragma unroll
    for (int o = 16; o; o >>= 1) ss += __shfl_xor_sync(0xffffffffu, ss, o);
    if ((tid & 31) == 0) red[tid >> 5] = ss;
    __syncthreads();
    if (tid == 0) {
        float t = red[0] + red[1] + red[2] + red[3];
        float inv = 1.0f / fmaxf(sqrtf(t), 1e-12f);
        red[4] = inv;
        if (isx) { g_invnx[rr] = inv; g_S[rr] = 0.0f; }
        else     { g_invnw[rr] = inv; }
    }
    __syncthreads();
    float inv = red[4];
    __nv_bfloat162 p0 = __floats2bfloat162_rn(v.x * inv, v.y * inv);
    __nv_bfloat162 p1 = __floats2bfloat162_rn(v.z * inv, v.w * inv);
    uint2 u;
    u.x = *reinterpret_cast<uint32_t*>(&p0);
    u.y = *reinterpret_cast<uint32_t*>(&p1);
    uint2* d = reinterpret_cast<uint2*>(isx ? g_xbf : g_wbf);
    d[(size_t)rr * 128 + tid] = u;
}

// ============================================================================
// Kernel 2: exact fp32 target-class cosine + margin correction per row
// ============================================================================
__global__ void target_kernel(const float* __restrict__ x, const float* __restrict__ w,
                              const void* __restrict__ lab) {
    __shared__ float red[4];
    int n = blockIdx.x, tid = threadIdx.x;   // 128 threads
    int c;
    if (g_lab64) c = (int)reinterpret_cast<const long long*>(lab)[n];
    else         c = reinterpret_cast<const int*>(lab)[n];
    float4 xv = reinterpret_cast<const float4*>(x)[(size_t)n * 128 + tid];
    float4 wv = reinterpret_cast<const float4*>(w)[(size_t)c * 128 + tid];
    float d = xv.x * wv.x + xv.y * wv.y + xv.z * wv.z + xv.w * wv.w;
#pragma unroll
    for (int o = 16; o; o >>= 1) d += __shfl_xor_sync(0xffffffffu, d, o);
    if ((tid & 31) == 0) red[tid >> 5] = d;
    __syncthreads();
    if (tid == 0) {
        float dot = red[0] + red[1] + red[2] + red[3];
        float t = dot * g_invnx[n] * g_invnw[c];
        t = fminf(1.0f, fmaxf(-1.0f, t));
        float st = sqrtf(fmaxf(0.0f, 1.0f - t * t));
        const float cos4 = -0.6536436208636119f;
        const float sin4 = -0.7568024953079282f;
        float cm = t * cos4 - st * sin4;
        g_cosm[n] = cm;
        g_corr[n] = expf(cm - 1.0f) - expf(t - 1.0f);
    }
}

// ============================================================================
// Kernel 3: pipelined HMMA bf16 GEMM (M=128, N=256, K=512) + fused exp-sum.
// 512 threads = 4x4 warps; each warp owns a 32x64 sub-tile.
// cp.async double-buffered K chunks of 64; ldmatrix frags; mma.sync m16n8k16.
// ============================================================================
__global__ void __launch_bounds__(512, 1) gemm_kernel() {
    extern __shared__ char smem[];
    const int tid  = threadIdx.x;
    const int wid  = tid >> 5, lane = tid & 31;
    const int wr   = wid >> 2;          // warp row 0..3 (32 M-rows each)
    const int wc   = wid & 3;           // warp col 0..3 (64 N-cols each)
    const int n0   = blockIdx.x * NTILE;
    const int m0   = blockIdx.y * MTILE;
    const uint32_t sb = smem_to_u32(smem);

    const char* Ag = (const char*)g_xbf;   // row stride 1024 B
    const char* Bg = (const char*)g_wbf;

    float c[2][8][4];
#pragma unroll
    for (int mt = 0; mt < 2; mt++)
#pragma unroll
        for (int j = 0; j < 8; j++)
#pragma unroll
            for (int r = 0; r < 4; r++) c[mt][j][r] = 0.0f;

    // -------- chunk loader: 6x cp.async 16B per thread --------
    auto load_chunk = [&](int kc, int buf) {
        uint32_t a_base = sb + buf * SMEM_A_BYTES;
        uint32_t b_base = sb + 2 * SMEM_A_BYTES + buf * SMEM_B_BYTES;
#pragma unroll
        for (int i = 0; i < 2; i++) {          // A: 1024 x 16B
            int idx = tid + i * 512;
            int row = idx >> 3, seg = idx & 7;
            uint32_t o = (uint32_t)(row * 128 + seg * 16);
            const char* src = Ag + (size_t)(m0 + row) * 1024 + kc * 128 + seg * 16;
            CP_ASYNC16(a_base + SMEM_SWIZZLE_128B(o), src);
        }
#pragma unroll
        for (int i = 0; i < 4; i++) {          // B: 2048 x 16B
            int idx = tid + i * 512;
            int row = idx >> 3, seg = idx & 7;
            uint32_t o = (uint32_t)(row * 128 + seg * 16);
            const char* src = Bg + (size_t)(n0 + row) * 1024 + kc * 128 + seg * 16;
            CP_ASYNC16(b_base + SMEM_SWIZZLE_128B(o), src);
        }
        CP_COMMIT();
    };

    // -------- per-chunk compute: 4 k-steps of 16 --------
    auto compute_chunk = [&](int buf) {
        uint32_t a_base = sb + buf * SMEM_A_BYTES;
        uint32_t b_base = sb + 2 * SMEM_A_BYTES + buf * SMEM_B_BYTES;
#pragma unroll
        for (int ks = 0; ks < 4; ks++) {
            const int koff = ks * 32;          // bytes
            uint32_t a[2][4];
#pragma unroll
            for (int mt = 0; mt < 2; mt++) {
                int row = wr * 32 + mt * 16 + (lane & 15);
                uint32_t o = (uint32_t)(row * 128 + ((lane >> 4) * 16) + koff);
                LDMATRIX_X4(a[mt][0], a[mt][1], a[mt][2], a[mt][3],
                            a_base + SMEM_SWIZZLE_128B(o));
            }
            uint32_t b[8][2];
#pragma unroll
            for (int jp = 0; jp < 4; jp++) {   // pair of n-tiles per x4
                int row = wc * 64 + jp * 16 + (lane & 7) + ((lane >> 4) << 3);
                uint32_t o = (uint32_t)(row * 128 + (((lane >> 3) & 1) * 16) + koff);
                LDMATRIX_X4(b[2 * jp][0], b[2 * jp][1], b[2 * jp + 1][0], b[2 * jp + 1][1],
                            b_base + SMEM_SWIZZLE_128B(o));
            }
#pragma unroll
            for (int mt = 0; mt < 2; mt++)
#pragma unroll
                for (int j = 0; j < 8; j++)
                    MMA_BF16(c[mt][j], a[mt], b[j]);
        }
    };

    // -------- pipelined mainloop --------
    load_chunk(0, 0);
    for (int kc = 0; kc < NCHUNKS; kc++) {
        if (kc + 1 < NCHUNKS) {
            load_chunk(kc + 1, (kc + 1) & 1);
            CP_WAIT(1);
        } else {
            CP_WAIT(0);
        }
        __syncthreads();
        compute_chunk(kc & 1);
        __syncthreads();   // protect buf before iter kc+1 issues chunk kc+2 into it
    }

    // -------- fused epilogue: rowsum of exp((cos-1)) --------
    // accum layout: row = wr*32 + mt*16 + (lane>>2) + (reg>=2 ? 8 : 0)
#pragma unroll
    for (int mt = 0; mt < 2; mt++) {
        float s0 = 0.0f, s1 = 0.0f;
#pragma unroll
        for (int j = 0; j < 8; j++) {
#pragma unroll
            for (int r = 0; r < 4; r++) {
                float t = c[mt][j][r];
                float aa = fmaf(t, LOG2E, -LOG2E);
                float e;
                asm("ex2.approx.f32 %0, %1;" : "=f"(e) : "f"(aa));
                if (r < 2) s0 += e; else s1 += e;
            }
        }
        // reduce across the 4 lanes sharing each row (lane & 3)
#pragma unroll
        for (int o = 1; o < 4; o <<= 1) {
            s0 += __shfl_xor_sync(0xffffffffu, s0, o);
            s1 += __shfl_xor_sync(0xffffffffu, s1, o);
        }
        if ((lane & 3) == 0) {
            int row = m0 + wr * 32 + mt * 16 + (lane >> 2);
            atomicAdd(&g_S[row], s0);
            atomicAdd(&g_S[row + 8], s1);
        }
    }
}

// ============================================================================
// Kernel 4: final loss reduction
// loss_n = 1 + log(S_n - PAD*e^-1 + corr_n) - cos_m_n ;  out = mean
// Padded cols each contribute exp(0-1)=e^-1 -> subtract (C_PAD-C_CLS)*e^-1.
// ============================================================================
__global__ void final_kernel(float* __restrict__ out) {
    __shared__ float red[256];
    const float PADSUB = (float)(C_PAD - C_CLS) * 0.36787944117144233f;
    float acc = 0.0f;
    for (int n = threadIdx.x; n < N_ROWS; n += 256) {
        float Sp = g_S[n] - PADSUB + g_corr[n];
        acc += 1.0f + logf(Sp) - g_cosm[n];
    }
    red[threadIdx.x] = acc;
    __syncthreads();
    for (int s = 128; s; s >>= 1) {
        if (threadIdx.x < s) red[threadIdx.x] += red[threadIdx.x + s];
        __syncthreads();
    }
    if (threadIdx.x == 0) out[0] = red[0] / (float)N_ROWS;
}

// ============================================================================
// Launch
// ============================================================================
extern "C" void kernel_launch(void* const* d_in, const int* in_sizes, int n_in,
                              void* d_out, int out_size) {
    const float* x = (const float*)d_in[0];
    const void*  lab = d_in[1];
    const float* w = (const float*)d_in[2];
    float* out = (float*)d_out;

    static bool configured = false;
    if (!configured) {
        cudaFuncSetAttribute(gemm_kernel, cudaFuncAttributeMaxDynamicSharedMemorySize,
                             SMEM_TOTAL);
        configured = true;
    }

    detect_kernel<<<1, 256>>>((const unsigned*)lab);
    prep_kernel<<<N_ROWS + C_PAD, 128>>>(x, w);
    target_kernel<<<N_ROWS, 128>>>(x, w, lab);
    gemm_kernel<<<dim3(N_TILES_C, N_TILES_M), 512, SMEM_TOTAL>>>();
    final_kernel<<<1, 256>>>(out);
}

// round 11
// speedup vs baseline: 1.0932x; 1.0932x over previous
#include <cuda_runtime.h>
#include <cuda_bf16.h>
#include <cstdint>

// ============================================================================
// Problem constants
// ============================================================================
#define N_ROWS   4096
#define E_DIM    512
#define C_CLS    50257
#define C_PAD    50432          // 394 * 128
#define N_TILES_C 394           // C_PAD / 128
#define N_TILES_M 32            // N_ROWS / 128

#define MTILE 128
#define NTILE 128
#define NCHUNKS 8               // 512 / 64 bf16 per K chunk (128 B per row-chunk)
#define NSTAGES 3
#define LOG2E 1.44269504f

// ============================================================================
// Device scratch (static — no allocation APIs allowed)
// ============================================================================
__device__ __align__(16) __nv_bfloat16 g_xbf[(size_t)N_ROWS * E_DIM];
__device__ __align__(16) __nv_bfloat16 g_wbf[(size_t)C_PAD * E_DIM];
__device__ float g_invnx[N_ROWS];
__device__ float g_invnw[C_CLS];
__device__ float g_S[N_ROWS];
__device__ float g_cosm[N_ROWS];
__device__ float g_corr[N_ROWS];
__device__ int   g_lab64;

// ============================================================================
// Helpers (base-target PTX only: cp.async / ldmatrix / mma.sync)
// ============================================================================
__device__ __forceinline__ uint32_t smem_to_u32(const void* smem_ptr) {
    uint32_t addr;
    asm("{ .reg .u64 tmp; cvta.to.shared.u64 tmp, %1; cvt.u32.u64 %0, tmp; }"
        : "=r"(addr) : "l"(smem_ptr));
    return addr;
}

#define SMEM_SWIZZLE_128B(o) ((o) ^ (((o) >> 3) & 0x70))

#define CP_ASYNC16(dst, src) \
    asm volatile("cp.async.cg.shared.global [%0], [%1], 16;" \
        :: "r"(dst), "l"(src) : "memory")
#define CP_COMMIT() asm volatile("cp.async.commit_group;" ::: "memory")
#define CP_WAIT(n)  asm volatile("cp.async.wait_group %0;" :: "n"(n) : "memory")

#define LDMATRIX_X4(r0, r1, r2, r3, addr) \
    asm volatile("ldmatrix.sync.aligned.m8n8.x4.shared.b16 {%0,%1,%2,%3}, [%4];" \
        : "=r"(r0), "=r"(r1), "=r"(r2), "=r"(r3) : "r"(addr))

#define MMA_BF16(c, a, b) \
    asm volatile("mma.sync.aligned.m16n8k16.row.col.f32.bf16.bf16.f32 " \
        "{%0,%1,%2,%3}, {%4,%5,%6,%7}, {%8,%9}, {%0,%1,%2,%3};" \
        : "+f"((c)[0]), "+f"((c)[1]), "+f"((c)[2]), "+f"((c)[3]) \
        : "r"((a)[0]), "r"((a)[1]), "r"((a)[2]), "r"((a)[3]), \
          "r"((b)[0]), "r"((b)[1]))

// SMEM: 3 stages of [A(16K) | B(16K)]
#define STAGE_BYTES  32768
#define SMEM_A_OFF   0
#define SMEM_B_OFF   16384
#define SMEM_TOTAL   (NSTAGES * STAGE_BYTES)   // 96 KB per CTA

// ============================================================================
// Kernel 0: detect label dtype (int64 vs int32) — deterministic given input
// ============================================================================
__global__ void detect_kernel(const unsigned* __restrict__ lab) {
    __shared__ unsigned acc[256];
    unsigned v = 0;
    for (int i = threadIdx.x; i < N_ROWS / 2; i += 256) v |= lab[2 * i + 1];
    acc[threadIdx.x] = v;
    __syncthreads();
    for (int s = 128; s; s >>= 1) {
        if (threadIdx.x < s) acc[threadIdx.x] |= acc[threadIdx.x + s];
        __syncthreads();
    }
    if (threadIdx.x == 0) g_lab64 = (acc[0] == 0) ? 1 : 0;
}

// ============================================================================
// Kernel 1: row-normalize x and W into bf16 scratch; store inverse norms;
//           zero S; zero-pad W rows [C_CLS, C_PAD)
// ============================================================================
__global__ void prep_kernel(const float* __restrict__ x, const float* __restrict__ w) {
    __shared__ float red[5];
    int r = blockIdx.x;
    int tid = threadIdx.x;             // 128 threads
    bool isx = (r < N_ROWS);
    int rr = isx ? r : r - N_ROWS;

    if (!isx && rr >= C_CLS) {         // zero-pad row
        reinterpret_cast<uint2*>(g_wbf)[(size_t)rr * 128 + tid] = make_uint2(0u, 0u);
        return;
    }

    const float4* s4 = reinterpret_cast<const float4*>(isx ? x : w);
    float4 v = s4[(size_t)rr * 128 + tid];
    float ss = v.x * v.x + v.y * v.y + v.z * v.z + v.w * v.w;
#pragma unroll
    for (int o = 16; o; o >>= 1) ss += __shfl_xor_sync(0xffffffffu, ss, o);
    if ((tid & 31) == 0) red[tid >> 5] = ss;
    __syncthreads();
    if (tid == 0) {
        float t = red[0] + red[1] + red[2] + red[3];
        float inv = 1.0f / fmaxf(sqrtf(t), 1e-12f);
        red[4] = inv;
        if (isx) { g_invnx[rr] = inv; g_S[rr] = 0.0f; }
        else     { g_invnw[rr] = inv; }
    }
    __syncthreads();
    float inv = red[4];
    __nv_bfloat162 p0 = __floats2bfloat162_rn(v.x * inv, v.y * inv);
    __nv_bfloat162 p1 = __floats2bfloat162_rn(v.z * inv, v.w * inv);
    uint2 u;
    u.x = *reinterpret_cast<uint32_t*>(&p0);
    u.y = *reinterpret_cast<uint32_t*>(&p1);
    uint2* d = reinterpret_cast<uint2*>(isx ? g_xbf : g_wbf);
    d[(size_t)rr * 128 + tid] = u;
}

// ============================================================================
// Kernel 2: exact fp32 target-class cosine + margin correction per row
// ============================================================================
__global__ void target_kernel(const float* __restrict__ x, const float* __restrict__ w,
                              const void* __restrict__ lab) {
    __shared__ float red[4];
    int n = blockIdx.x, tid = threadIdx.x;   // 128 threads
    int c;
    if (g_lab64) c = (int)reinterpret_cast<const long long*>(lab)[n];
    else         c = reinterpret_cast<const int*>(lab)[n];
    float4 xv = reinterpret_cast<const float4*>(x)[(size_t)n * 128 + tid];
    float4 wv = reinterpret_cast<const float4*>(w)[(size_t)c * 128 + tid];
    float d = xv.x * wv.x + xv.y * wv.y + xv.z * wv.z + xv.w * wv.w;
#pragma unroll
    for (int o = 16; o; o >>= 1) d += __shfl_xor_sync(0xffffffffu, d, o);
    if ((tid & 31) == 0) red[tid >> 5] = d;
    __syncthreads();
    if (tid == 0) {
        float dot = red[0] + red[1] + red[2] + red[3];
        float t = dot * g_invnx[n] * g_invnw[c];
        t = fminf(1.0f, fmaxf(-1.0f, t));
        float st = sqrtf(fmaxf(0.0f, 1.0f - t * t));
        const float cos4 = -0.6536436208636119f;
        const float sin4 = -0.7568024953079282f;
        float cm = t * cos4 - st * sin4;
        g_cosm[n] = cm;
        g_corr[n] = expf(cm - 1.0f) - expf(t - 1.0f);
    }
}

// ============================================================================
// Kernel 3: pipelined HMMA bf16 GEMM (tile 128x128, K=512) + fused exp-sum.
// 256 threads = 4x2 warps (warp tile 32Mx64N), 2 CTAs/SM for latency overlap.
// 3-stage cp.async ring, ONE __syncthreads per chunk.
// ============================================================================
__global__ void __launch_bounds__(256, 2) gemm_kernel() {
    extern __shared__ char smem[];
    const int tid  = threadIdx.x;
    const int wid  = tid >> 5, lane = tid & 31;
    const int wr   = wid >> 1;          // warp row 0..3 (32 M-rows each)
    const int wc   = wid & 1;           // warp col 0..1 (64 N-cols each)
    const int n0   = blockIdx.x * NTILE;
    const int m0   = blockIdx.y * MTILE;
    const uint32_t sb = smem_to_u32(smem);

    const char* Ag = (const char*)g_xbf;   // row stride 1024 B
    const char* Bg = (const char*)g_wbf;

    float c[2][8][4];
#pragma unroll
    for (int mt = 0; mt < 2; mt++)
#pragma unroll
        for (int j = 0; j < 8; j++)
#pragma unroll
            for (int r = 0; r < 4; r++) c[mt][j][r] = 0.0f;

    // -------- chunk loader: 8x cp.async 16B per thread (A 16K + B 16K) -----
    auto load_chunk = [&](int kc, int stg) {
        uint32_t a_base = sb + stg * STAGE_BYTES + SMEM_A_OFF;
        uint32_t b_base = sb + stg * STAGE_BYTES + SMEM_B_OFF;
#pragma unroll
        for (int i = 0; i < 4; i++) {          // A: 1024 x 16B
            int idx = tid + i * 256;
            int row = idx >> 3, seg = idx & 7;
            uint32_t o = (uint32_t)(row * 128 + seg * 16);
            const char* src = Ag + (size_t)(m0 + row) * 1024 + kc * 128 + seg * 16;
            CP_ASYNC16(a_base + SMEM_SWIZZLE_128B(o), src);
        }
#pragma unroll
        for (int i = 0; i < 4; i++) {          // B: 1024 x 16B
            int idx = tid + i * 256;
            int row = idx >> 3, seg = idx & 7;
            uint32_t o = (uint32_t)(row * 128 + seg * 16);
            const char* src = Bg + (size_t)(n0 + row) * 1024 + kc * 128 + seg * 16;
            CP_ASYNC16(b_base + SMEM_SWIZZLE_128B(o), src);
        }
        CP_COMMIT();
    };

    // -------- per-chunk compute: 4 k-steps of 16 --------
    auto compute_chunk = [&](int stg) {
        uint32_t a_base = sb + stg * STAGE_BYTES + SMEM_A_OFF;
        uint32_t b_base = sb + stg * STAGE_BYTES + SMEM_B_OFF;
#pragma unroll
        for (int ks = 0; ks < 4; ks++) {
            const int koff = ks * 32;          // bytes
            uint32_t a[2][4];
#pragma unroll
            for (int mt = 0; mt < 2; mt++) {
                int row = wr * 32 + mt * 16 + (lane & 15);
                uint32_t o = (uint32_t)(row * 128 + ((lane >> 4) * 16) + koff);
                LDMATRIX_X4(a[mt][0], a[mt][1], a[mt][2], a[mt][3],
                            a_base + SMEM_SWIZZLE_128B(o));
            }
            uint32_t b[8][2];
#pragma unroll
            for (int jp = 0; jp < 4; jp++) {   // pair of n8-tiles per x4
                int row = wc * 64 + jp * 16 + (lane & 7) + ((lane >> 4) << 3);
                uint32_t o = (uint32_t)(row * 128 + (((lane >> 3) & 1) * 16) + koff);
                LDMATRIX_X4(b[2 * jp][0], b[2 * jp][1], b[2 * jp + 1][0], b[2 * jp + 1][1],
                            b_base + SMEM_SWIZZLE_128B(o));
            }
#pragma unroll
            for (int mt = 0; mt < 2; mt++)
#pragma unroll
                for (int j = 0; j < 8; j++)
                    MMA_BF16(c[mt][j], a[mt], b[j]);
        }
    };

    // -------- 3-stage pipelined mainloop, one barrier per chunk --------
    load_chunk(0, 0);
    load_chunk(1, 1);
    for (int kc = 0; kc < NCHUNKS; kc++) {
        CP_WAIT(1);            // chunk kc resident
        __syncthreads();       // data visible to all warps; stage (kc+2)%3 free
        if (kc + 2 < NCHUNKS) load_chunk(kc + 2, (kc + 2) % NSTAGES);
        compute_chunk(kc % NSTAGES);
    }

    // -------- fused epilogue: rowsum of exp((cos-1)) --------
    // accum layout: row = wr*32 + mt*16 + (lane>>2) + (reg>=2 ? 8 : 0)
#pragma unroll
    for (int mt = 0; mt < 2; mt++) {
        float s0 = 0.0f, s1 = 0.0f;
#pragma unroll
        for (int j = 0; j < 8; j++) {
#pragma unroll
            for (int r = 0; r < 4; r++) {
                float t = c[mt][j][r];
                float aa = fmaf(t, LOG2E, -LOG2E);
                float e;
                asm("ex2.approx.f32 %0, %1;" : "=f"(e) : "f"(aa));
                if (r < 2) s0 += e; else s1 += e;
            }
        }
        // reduce across the 4 lanes sharing each row (lane & 3)
#pragma unroll
        for (int o = 1; o < 4; o <<= 1) {
            s0 += __shfl_xor_sync(0xffffffffu, s0, o);
            s1 += __shfl_xor_sync(0xffffffffu, s1, o);
        }
        if ((lane & 3) == 0) {
            int row = m0 + wr * 32 + mt * 16 + (lane >> 2);
            atomicAdd(&g_S[row], s0);
            atomicAdd(&g_S[row + 8], s1);
        }
    }
}

// ============================================================================
// Kernel 4: final loss reduction
// loss_n = 1 + log(S_n - PAD*e^-1 + corr_n) - cos_m_n ;  out = mean
// Padded cols each contribute exp(0-1)=e^-1 -> subtract (C_PAD-C_CLS)*e^-1.
// ============================================================================
__global__ void final_kernel(float* __restrict__ out) {
    __shared__ float red[256];
    const float PADSUB = (float)(C_PAD - C_CLS) * 0.36787944117144233f;
    float acc = 0.0f;
    for (int n = threadIdx.x; n < N_ROWS; n += 256) {
        float Sp = g_S[n] - PADSUB + g_corr[n];
        acc += 1.0f + logf(Sp) - g_cosm[n];
    }
    red[threadIdx.x] = acc;
    __syncthreads();
    for (int s = 128; s; s >>= 1) {
        if (threadIdx.x < s) red[threadIdx.x] += red[threadIdx.x + s];
        __syncthreads();
    }
    if (threadIdx.x == 0) out[0] = red[0] / (float)N_ROWS;
}

// ============================================================================
// Launch
// ============================================================================
extern "C" void kernel_launch(void* const* d_in, const int* in_sizes, int n_in,
                              void* d_out, int out_size) {
    const float* x = (const float*)d_in[0];
    const void*  lab = d_in[1];
    const float* w = (const float*)d_in[2];
    float* out = (float*)d_out;

    static bool configured = false;
    if (!configured) {
        cudaFuncSetAttribute(gemm_kernel, cudaFuncAttributeMaxDynamicSharedMemorySize,
                             SMEM_TOTAL);
        configured = true;
    }

    detect_kernel<<<1, 256>>>((const unsigned*)lab);
    prep_kernel<<<N_ROWS + C_PAD, 128>>>(x, w);
    target_kernel<<<N_ROWS, 128>>>(x, w, lab);
    gemm_kernel<<<dim3(N_TILES_C, N_TILES_M), 256, SMEM_TOTAL>>>();
    final_kernel<<<1, 256>>>(out);
}

// round 12
// speedup vs baseline: 1.1276x; 1.0315x over previous
#include <cuda_runtime.h>
#include <cuda_bf16.h>
#include <cstdint>

// ============================================================================
// Problem constants
// ============================================================================
#define N_ROWS   4096
#define E_DIM    512
#define C_CLS    50257
#define C_PAD    50432          // 394 * 128
#define N_TILES_C 394           // C_PAD / 128
#define N_TILES_M 32            // N_ROWS / 128

#define MTILE 128
#define NTILE 128
#define NCHUNKS 8               // 512 / 64 bf16 per K chunk (128 B per row-chunk)
#define NSTAGES 3
#define LOG2E 1.44269504f

// ============================================================================
// Device scratch (static — no allocation APIs allowed)
// ============================================================================
__device__ __align__(16) __nv_bfloat16 g_xbf[(size_t)N_ROWS * E_DIM];
__device__ __align__(16) __nv_bfloat16 g_wbf[(size_t)C_PAD * E_DIM];
__device__ float g_invnx[N_ROWS];
__device__ float g_invnw[C_CLS];
__device__ float g_S[N_ROWS];
__device__ float g_cosm[N_ROWS];
__device__ float g_corr[N_ROWS];
__device__ int   g_lab64;

// ============================================================================
// Helpers (base-target PTX only: cp.async / ldmatrix / mma.sync)
// ============================================================================
__device__ __forceinline__ uint32_t smem_to_u32(const void* smem_ptr) {
    uint32_t addr;
    asm("{ .reg .u64 tmp; cvta.to.shared.u64 tmp, %1; cvt.u32.u64 %0, tmp; }"
        : "=r"(addr) : "l"(smem_ptr));
    return addr;
}

#define SMEM_SWIZZLE_128B(o) ((o) ^ (((o) >> 3) & 0x70))

#define CP_ASYNC16(dst, src) \
    asm volatile("cp.async.cg.shared.global [%0], [%1], 16;" \
        :: "r"(dst), "l"(src) : "memory")
#define CP_COMMIT() asm volatile("cp.async.commit_group;" ::: "memory")
#define CP_WAIT(n)  asm volatile("cp.async.wait_group %0;" :: "n"(n) : "memory")

#define LDMATRIX_X4(r0, r1, r2, r3, addr) \
    asm volatile("ldmatrix.sync.aligned.m8n8.x4.shared.b16 {%0,%1,%2,%3}, [%4];" \
        : "=r"(r0), "=r"(r1), "=r"(r2), "=r"(r3) : "r"(addr))

#define MMA_BF16(c, a, b) \
    asm volatile("mma.sync.aligned.m16n8k16.row.col.f32.bf16.bf16.f32 " \
        "{%0,%1,%2,%3}, {%4,%5,%6,%7}, {%8,%9}, {%0,%1,%2,%3};" \
        : "+f"((c)[0]), "+f"((c)[1]), "+f"((c)[2]), "+f"((c)[3]) \
        : "r"((a)[0]), "r"((a)[1]), "r"((a)[2]), "r"((a)[3]), \
          "r"((b)[0]), "r"((b)[1]))

// SMEM: 3 stages of [A(16K) | B(16K)]
#define STAGE_BYTES  32768
#define SMEM_A_OFF   0
#define SMEM_B_OFF   16384
#define SMEM_TOTAL   (NSTAGES * STAGE_BYTES)   // 96 KB per CTA

// ============================================================================
// Kernel 0: detect label dtype (int64 vs int32) — deterministic given input
// ============================================================================
__global__ void detect_kernel(const unsigned* __restrict__ lab) {
    __shared__ unsigned acc[256];
    unsigned v = 0;
    for (int i = threadIdx.x; i < N_ROWS / 2; i += 256) v |= lab[2 * i + 1];
    acc[threadIdx.x] = v;
    __syncthreads();
    for (int s = 128; s; s >>= 1) {
        if (threadIdx.x < s) acc[threadIdx.x] |= acc[threadIdx.x + s];
        __syncthreads();
    }
    if (threadIdx.x == 0) g_lab64 = (acc[0] == 0) ? 1 : 0;
}

// ============================================================================
// Kernel 1: row-normalize x and W into bf16 scratch; store inverse norms;
//           zero S; zero-pad W rows [C_CLS, C_PAD)
// ============================================================================
__global__ void prep_kernel(const float* __restrict__ x, const float* __restrict__ w) {
    __shared__ float red[5];
    int r = blockIdx.x;
    int tid = threadIdx.x;             // 128 threads
    bool isx = (r < N_ROWS);
    int rr = isx ? r : r - N_ROWS;

    if (!isx && rr >= C_CLS) {         // zero-pad row
        reinterpret_cast<uint2*>(g_wbf)[(size_t)rr * 128 + tid] = make_uint2(0u, 0u);
        return;
    }

    const float4* s4 = reinterpret_cast<const float4*>(isx ? x : w);
    float4 v = s4[(size_t)rr * 128 + tid];
    float ss = v.x * v.x + v.y * v.y + v.z * v.z + v.w * v.w;
#pragma unroll
    for (int o = 16; o; o >>= 1) ss += __shfl_xor_sync(0xffffffffu, ss, o);
    if ((tid & 31) == 0) red[tid >> 5] = ss;
    __syncthreads();
    if (tid == 0) {
        float t = red[0] + red[1] + red[2] + red[3];
        float inv = 1.0f / fmaxf(sqrtf(t), 1e-12f);
        red[4] = inv;
        if (isx) { g_invnx[rr] = inv; g_S[rr] = 0.0f; }
        else     { g_invnw[rr] = inv; }
    }
    __syncthreads();
    float inv = red[4];
    __nv_bfloat162 p0 = __floats2bfloat162_rn(v.x * inv, v.y * inv);
    __nv_bfloat162 p1 = __floats2bfloat162_rn(v.z * inv, v.w * inv);
    uint2 u;
    u.x = *reinterpret_cast<uint32_t*>(&p0);
    u.y = *reinterpret_cast<uint32_t*>(&p1);
    uint2* d = reinterpret_cast<uint2*>(isx ? g_xbf : g_wbf);
    d[(size_t)rr * 128 + tid] = u;
}

// ============================================================================
// Kernel 2: exact fp32 target-class cosine + margin correction per row
// ============================================================================
__global__ void target_kernel(const float* __restrict__ x, const float* __restrict__ w,
                              const void* __restrict__ lab) {
    __shared__ float red[4];
    int n = blockIdx.x, tid = threadIdx.x;   // 128 threads
    int c;
    if (g_lab64) c = (int)reinterpret_cast<const long long*>(lab)[n];
    else         c = reinterpret_cast<const int*>(lab)[n];
    float4 xv = reinterpret_cast<const float4*>(x)[(size_t)n * 128 + tid];
    float4 wv = reinterpret_cast<const float4*>(w)[(size_t)c * 128 + tid];
    float d = xv.x * wv.x + xv.y * wv.y + xv.z * wv.z + xv.w * wv.w;
#pragma unroll
    for (int o = 16; o; o >>= 1) d += __shfl_xor_sync(0xffffffffu, d, o);
    if ((tid & 31) == 0) red[tid >> 5] = d;
    __syncthreads();
    if (tid == 0) {
        float dot = red[0] + red[1] + red[2] + red[3];
        float t = dot * g_invnx[n] * g_invnw[c];
        t = fminf(1.0f, fmaxf(-1.0f, t));
        float st = sqrtf(fmaxf(0.0f, 1.0f - t * t));
        const float cos4 = -0.6536436208636119f;
        const float sin4 = -0.7568024953079282f;
        float cm = t * cos4 - st * sin4;
        g_cosm[n] = cm;
        g_corr[n] = expf(cm - 1.0f) - expf(t - 1.0f);
    }
}

// ============================================================================
// Kernel 3: pipelined HMMA bf16 GEMM (tile 128x128, K=512) + fused exp-sum.
// 256 threads = 4x2 warps (warp tile 32Mx64N), 2 CTAs/SM.
// 3-stage cp.async ring, ONE __syncthreads per chunk, and a software-
// pipelined k-step loop: frags for ks+1 load (parity buffers) before the
// MMAs of ks issue, hiding LDSM latency inside the tensor work.
// ============================================================================
__global__ void __launch_bounds__(256, 2) gemm_kernel() {
    extern __shared__ char smem[];
    const int tid  = threadIdx.x;
    const int wid  = tid >> 5, lane = tid & 31;
    const int wr   = wid >> 1;          // warp row 0..3 (32 M-rows each)
    const int wc   = wid & 1;           // warp col 0..1 (64 N-cols each)
    const int n0   = blockIdx.x * NTILE;
    const int m0   = blockIdx.y * MTILE;
    const uint32_t sb = smem_to_u32(smem);

    const char* Ag = (const char*)g_xbf;   // row stride 1024 B
    const char* Bg = (const char*)g_wbf;

    float c[2][8][4];
#pragma unroll
    for (int mt = 0; mt < 2; mt++)
#pragma unroll
        for (int j = 0; j < 8; j++)
#pragma unroll
            for (int r = 0; r < 4; r++) c[mt][j][r] = 0.0f;

    // Precomputed per-warp ldmatrix base addresses (koff added per k-step).
    // A: row = wr*32 + mt*16 + (lane&15); col-half = (lane>>4)*16
    // B: row = wc*64 + jp*16 + (lane&7) + ((lane>>4)<<3); col = ((lane>>3)&1)*16
    uint32_t a_row_off[2];
#pragma unroll
    for (int mt = 0; mt < 2; mt++)
        a_row_off[mt] = (uint32_t)((wr * 32 + mt * 16 + (lane & 15)) * 128 +
                                   ((lane >> 4) * 16));
    uint32_t b_row_off[4];
#pragma unroll
    for (int jp = 0; jp < 4; jp++)
        b_row_off[jp] = (uint32_t)((wc * 64 + jp * 16 + (lane & 7) +
                                    ((lane >> 4) << 3)) * 128 +
                                   (((lane >> 3) & 1) * 16));

    // -------- chunk loader: 8x cp.async 16B per thread (A 16K + B 16K) -----
    auto load_chunk = [&](int kc, int stg) {
        uint32_t a_base = sb + stg * STAGE_BYTES + SMEM_A_OFF;
        uint32_t b_base = sb + stg * STAGE_BYTES + SMEM_B_OFF;
#pragma unroll
        for (int i = 0; i < 4; i++) {          // A: 1024 x 16B
            int idx = tid + i * 256;
            int row = idx >> 3, seg = idx & 7;
            uint32_t o = (uint32_t)(row * 128 + seg * 16);
            const char* src = Ag + (size_t)(m0 + row) * 1024 + kc * 128 + seg * 16;
            CP_ASYNC16(a_base + SMEM_SWIZZLE_128B(o), src);
        }
#pragma unroll
        for (int i = 0; i < 4; i++) {          // B: 1024 x 16B
            int idx = tid + i * 256;
            int row = idx >> 3, seg = idx & 7;
            uint32_t o = (uint32_t)(row * 128 + seg * 16);
            const char* src = Bg + (size_t)(n0 + row) * 1024 + kc * 128 + seg * 16;
            CP_ASYNC16(b_base + SMEM_SWIZZLE_128B(o), src);
        }
        CP_COMMIT();
    };

    // -------- per-chunk compute: software-pipelined 4 k-steps of 16 --------
    auto compute_chunk = [&](int stg) {
        uint32_t a_base = sb + stg * STAGE_BYTES + SMEM_A_OFF;
        uint32_t b_base = sb + stg * STAGE_BYTES + SMEM_B_OFF;
        uint32_t a[2][2][4];   // [parity][mt][reg]
        uint32_t b[2][8][2];   // [parity][n8][reg]

#define LOAD_FRAGS(ks, p)                                                     \
        do {                                                                  \
            const int _koff = (ks) * 32;                                      \
            _Pragma("unroll")                                                 \
            for (int mt = 0; mt < 2; mt++)                                    \
                LDMATRIX_X4(a[p][mt][0], a[p][mt][1], a[p][mt][2], a[p][mt][3],\
                            a_base + SMEM_SWIZZLE_128B(a_row_off[mt] + _koff));\
            _Pragma("unroll")                                                 \
            for (int jp = 0; jp < 4; jp++)                                    \
                LDMATRIX_X4(b[p][2*jp][0], b[p][2*jp][1],                     \
                            b[p][2*jp+1][0], b[p][2*jp+1][1],                 \
                            b_base + SMEM_SWIZZLE_128B(b_row_off[jp] + _koff));\
        } while (0)

        LOAD_FRAGS(0, 0);
#pragma unroll
        for (int ks = 0; ks < 4; ks++) {
            const int cur = ks & 1;
            if (ks < 3) LOAD_FRAGS(ks + 1, cur ^ 1);
#pragma unroll
            for (int mt = 0; mt < 2; mt++)
#pragma unroll
                for (int j = 0; j < 8; j++)
                    MMA_BF16(c[mt][j], a[cur][mt], b[cur][j]);
        }
#undef LOAD_FRAGS
    };

    // -------- 3-stage pipelined mainloop, one barrier per chunk --------
    load_chunk(0, 0);
    load_chunk(1, 1);
    for (int kc = 0; kc < NCHUNKS; kc++) {
        CP_WAIT(1);            // chunk kc resident
        __syncthreads();       // data visible to all warps; stage (kc+2)%3 free
        if (kc + 2 < NCHUNKS) load_chunk(kc + 2, (kc + 2) % NSTAGES);
        compute_chunk(kc % NSTAGES);
    }

    // -------- fused epilogue: rowsum of exp((cos-1)) --------
    // accum layout: row = wr*32 + mt*16 + (lane>>2) + (reg>=2 ? 8 : 0)
#pragma unroll
    for (int mt = 0; mt < 2; mt++) {
        float s0 = 0.0f, s1 = 0.0f;
#pragma unroll
        for (int j = 0; j < 8; j++) {
#pragma unroll
            for (int r = 0; r < 4; r++) {
                float t = c[mt][j][r];
                float aa = fmaf(t, LOG2E, -LOG2E);
                float e;
                asm("ex2.approx.f32 %0, %1;" : "=f"(e) : "f"(aa));
                if (r < 2) s0 += e; else s1 += e;
            }
        }
        // reduce across the 4 lanes sharing each row (lane & 3)
#pragma unroll
        for (int o = 1; o < 4; o <<= 1) {
            s0 += __shfl_xor_sync(0xffffffffu, s0, o);
            s1 += __shfl_xor_sync(0xffffffffu, s1, o);
        }
        if ((lane & 3) == 0) {
            int row = m0 + wr * 32 + mt * 16 + (lane >> 2);
            atomicAdd(&g_S[row], s0);
            atomicAdd(&g_S[row + 8], s1);
        }
    }
}

// ============================================================================
// Kernel 4: final loss reduction
// loss_n = 1 + log(S_n - PAD*e^-1 + corr_n) - cos_m_n ;  out = mean
// Padded cols each contribute exp(0-1)=e^-1 -> subtract (C_PAD-C_CLS)*e^-1.
// ============================================================================
__global__ void final_kernel(float* __restrict__ out) {
    __shared__ float red[256];
    const float PADSUB = (float)(C_PAD - C_CLS) * 0.36787944117144233f;
    float acc = 0.0f;
    for (int n = threadIdx.x; n < N_ROWS; n += 256) {
        float Sp = g_S[n] - PADSUB + g_corr[n];
        acc += 1.0f + logf(Sp) - g_cosm[n];
    }
    red[threadIdx.x] = acc;
    __syncthreads();
    for (int s = 128; s; s >>= 1) {
        if (threadIdx.x < s) red[threadIdx.x] += red[threadIdx.x + s];
        __syncthreads();
    }
    if (threadIdx.x == 0) out[0] = red[0] / (float)N_ROWS;
}

// ============================================================================
// Launch
// ============================================================================
extern "C" void kernel_launch(void* const* d_in, const int* in_sizes, int n_in,
                              void* d_out, int out_size) {
    const float* x = (const float*)d_in[0];
    const void*  lab = d_in[1];
    const float* w = (const float*)d_in[2];
    float* out = (float*)d_out;

    static bool configured = false;
    if (!configured) {
        cudaFuncSetAttribute(gemm_kernel, cudaFuncAttributeMaxDynamicSharedMemorySize,
                             SMEM_TOTAL);
        configured = true;
    }

    detect_kernel<<<1, 256>>>((const unsigned*)lab);
    prep_kernel<<<N_ROWS + C_PAD, 128>>>(x, w);
    target_kernel<<<N_ROWS, 128>>>(x, w, lab);
    gemm_kernel<<<dim3(N_TILES_C, N_TILES_M), 256, SMEM_TOTAL>>>();
    final_kernel<<<1, 256>>>(out);
}